// round 4
// baseline (speedup 1.0000x reference)
#include <cuda_runtime.h>
#include <cuda_bf16.h>
#include <cstdint>

// Problem constants (fixed shapes for this bench)
#define B_NODES 16384
#define K_NEIGH 15
#define D_FEAT  256          // 64 float4 per row
#define D_VEC4  (D_FEAT / 4) // 64

// Detected index dtype flag: 1 => int64 indices, 0 => int32 indices.
__device__ int g_idx_is_64 = 1;

// --- Index dtype detection -------------------------------------------------
// int64 (little-endian) layout: words 1,3,5,... of the raw buffer are the
// high halves of the first indices => all zero (indices < 19997).
// int32 layout: those words are real random indices; the chance that 32
// consecutive ones are all zero is ~U^-32 ~ 0. Reads only the first 256 bytes,
// valid under either layout (buffer >= 245760 * 4 bytes).
__global__ void detect_idx_dtype_kernel(const int* __restrict__ raw) {
    if (threadIdx.x == 0) {
        int is64 = 1;
        #pragma unroll
        for (int i = 1; i < 64; i += 2) {
            if (raw[i] != 0) is64 = 0;
        }
        g_idx_is_64 = is64;
    }
}

// --- Main gather-mean kernel -----------------------------------------------
// One warp per output row. Lane l accumulates float4 columns l and l+32.
__global__ __launch_bounds__(256, 8)
void mean_agg_kernel(const int* __restrict__ idx_raw,
                     const float4* __restrict__ feats,
                     float4* __restrict__ out) {
    const int warp = (blockIdx.x * blockDim.x + threadIdx.x) >> 5;
    const int lane = threadIdx.x & 31;
    if (warp >= B_NODES) return;

    const bool is64 = (g_idx_is_64 != 0);
    const int base = warp * K_NEIGH;

    // Load all neighbor ids up front (uniform across the warp -> broadcast).
    int ids[K_NEIGH];
    #pragma unroll
    for (int k = 0; k < K_NEIGH; k++) {
        ids[k] = is64 ? __ldg(&idx_raw[(base + k) * 2])  // low word of int64
                      : __ldg(&idx_raw[base + k]);
    }

    float4 a0 = make_float4(0.f, 0.f, 0.f, 0.f);
    float4 a1 = make_float4(0.f, 0.f, 0.f, 0.f);

    #pragma unroll
    for (int k = 0; k < K_NEIGH; k++) {
        const float4* row = feats + (size_t)ids[k] * D_VEC4;
        float4 v0 = __ldg(row + lane);
        float4 v1 = __ldg(row + lane + 32);
        a0.x += v0.x; a0.y += v0.y; a0.z += v0.z; a0.w += v0.w;
        a1.x += v1.x; a1.y += v1.y; a1.z += v1.z; a1.w += v1.w;
    }

    const float s = 1.0f / (float)K_NEIGH;
    a0.x *= s; a0.y *= s; a0.z *= s; a0.w *= s;
    a1.x *= s; a1.y *= s; a1.z *= s; a1.w *= s;

    float4* orow = out + (size_t)warp * D_VEC4;
    orow[lane]      = a0;
    orow[lane + 32] = a1;
}

extern "C" void kernel_launch(void* const* d_in, const int* in_sizes, int n_in,
                              void* d_out, int out_size) {
    const int*    idx_raw = (const int*)d_in[0];     // int64 or int32, detected
    const float4* feats   = (const float4*)d_in[1];  // [U, 256] fp32
    float4*       out     = (float4*)d_out;          // [B, 256] fp32

    detect_idx_dtype_kernel<<<1, 32>>>(idx_raw);

    const int threads = 256;                 // 8 warps = 8 rows per block
    const int blocks  = (B_NODES * 32 + threads - 1) / threads;  // 2048
    mean_agg_kernel<<<blocks, threads>>>(idx_raw, feats, out);
}

// round 5
// speedup vs baseline: 1.3131x; 1.3131x over previous
#include <cuda_runtime.h>
#include <cuda_bf16.h>
#include <cstdint>

// Problem constants (fixed shapes for this bench)
#define B_NODES 16384
#define K_NEIGH 15
#define D_FEAT  256          // 64 float4 per row
#define D_VEC4  (D_FEAT / 4) // 64
#define CHUNK   5            // neighbors prefetched per batch (10 float4 in flight)

// Detected index dtype flag: 1 => int64 indices, 0 => int32 indices.
__device__ int g_idx_is_64 = 1;

// --- Index dtype detection -------------------------------------------------
// int64 (little-endian): odd 32-bit words of the first 64 words are high
// halves of indices < 19997 => all zero. int32: those words are random
// indices; P(all zero) ~ U^-32 ~ 0. Reads 256 bytes, valid either way.
__global__ void detect_idx_dtype_kernel(const int* __restrict__ raw) {
    if (threadIdx.x == 0) {
        int is64 = 1;
        #pragma unroll
        for (int i = 1; i < 64; i += 2) {
            if (raw[i] != 0) is64 = 0;
        }
        g_idx_is_64 = is64;
    }
}

// --- Main gather-mean kernel -----------------------------------------------
// One warp per output row. Lane l accumulates float4 columns l and l+32.
// K processed in chunks of CHUNK with all loads issued before any adds,
// giving MLP ~= 2*CHUNK outstanding 128-bit loads per warp.
__global__ __launch_bounds__(256)
void mean_agg_kernel(const int* __restrict__ idx_raw,
                     const float4* __restrict__ feats,
                     float4* __restrict__ out) {
    const int warp = (blockIdx.x * blockDim.x + threadIdx.x) >> 5;
    const int lane = threadIdx.x & 31;
    if (warp >= B_NODES) return;

    const bool is64 = (g_idx_is_64 != 0);
    const int base = warp * K_NEIGH;

    // Load all neighbor ids up front (uniform across the warp -> broadcast).
    int ids[K_NEIGH];
    #pragma unroll
    for (int k = 0; k < K_NEIGH; k++) {
        ids[k] = is64 ? __ldg(&idx_raw[(base + k) * 2])  // low word of int64
                      : __ldg(&idx_raw[base + k]);
    }

    float4 a0 = make_float4(0.f, 0.f, 0.f, 0.f);
    float4 a1 = make_float4(0.f, 0.f, 0.f, 0.f);

    #pragma unroll
    for (int c = 0; c < K_NEIGH; c += CHUNK) {
        float4 v0[CHUNK], v1[CHUNK];
        // Batch all loads of this chunk first -> deep MLP.
        #pragma unroll
        for (int j = 0; j < CHUNK; j++) {
            const float4* row = feats + (size_t)ids[c + j] * D_VEC4;
            v0[j] = __ldg(row + lane);
            v1[j] = __ldg(row + lane + 32);
        }
        #pragma unroll
        for (int j = 0; j < CHUNK; j++) {
            a0.x += v0[j].x; a0.y += v0[j].y; a0.z += v0[j].z; a0.w += v0[j].w;
            a1.x += v1[j].x; a1.y += v1[j].y; a1.z += v1[j].z; a1.w += v1[j].w;
        }
    }

    const float s = 1.0f / (float)K_NEIGH;
    a0.x *= s; a0.y *= s; a0.z *= s; a0.w *= s;
    a1.x *= s; a1.y *= s; a1.z *= s; a1.w *= s;

    float4* orow = out + (size_t)warp * D_VEC4;
    orow[lane]      = a0;
    orow[lane + 32] = a1;
}

extern "C" void kernel_launch(void* const* d_in, const int* in_sizes, int n_in,
                              void* d_out, int out_size) {
    const int*    idx_raw = (const int*)d_in[0];     // int64 or int32, detected
    const float4* feats   = (const float4*)d_in[1];  // [U, 256] fp32
    float4*       out     = (float4*)d_out;          // [B, 256] fp32

    detect_idx_dtype_kernel<<<1, 32>>>(idx_raw);

    const int threads = 256;                 // 8 warps = 8 rows per block
    const int blocks  = (B_NODES * 32 + threads - 1) / threads;  // 2048
    mean_agg_kernel<<<blocks, threads>>>(idx_raw, feats, out);
}